// round 10
// baseline (speedup 1.0000x reference)
#include <cuda_runtime.h>

#define NB    4096
#define NPOSE 13
#define NHID  256
#define NIN   269
#define NCTX  256
#define BT    28      // batch rows per CTA
#define NTHR  512     // two halves: half 0 -> rows 0..13, half 1 -> rows 14..27

// Input-layer weights duplicated (tiny: 13 k-iters + one-time 256 k-iters).
__device__ float2 g_Wptd[NPOSE * NHID];          // W_in pose part: [k][j] -> (w,w)
__device__ float2 g_Wctd[NCTX  * NHID];          // W_in ctx  part: [k][j] -> (w,w)
// Gate weights PACKED, non-duplicated: 2 LDGs per k per thread.
__device__ float4 g_W4[NHID * NHID];             // [k][j] -> (w_ir, w_iz, w_in, w_hr)
__device__ float2 g_W2[NHID * NHID];             // [k][j] -> (w_hz, w_hn)

// Packed dual-fp32 FMA (Blackwell f32x2 pipe; only reachable via PTX).
__device__ __forceinline__ float2 ffma2(float2 a, float2 b, float2 c) {
    float2 d;
    asm("fma.rn.f32x2 %0, %1, %2, %3;"
        : "=l"(*reinterpret_cast<unsigned long long*>(&d))
        : "l"(*reinterpret_cast<unsigned long long*>(&a)),
          "l"(*reinterpret_cast<unsigned long long*>(&b)),
          "l"(*reinterpret_cast<unsigned long long*>(&c)));
    return d;
}

__device__ __forceinline__ float sigm(float a) {
    return 1.0f / (1.0f + __expf(-a));
}
__device__ __forceinline__ float tanh_acc(float a) {
    float e = __expf(-2.0f * fabsf(a));      // e in (0,1], overflow-safe
    float t = (1.0f - e) / (1.0f + e);
    return copysignf(t, a);
}

__global__ void prep_kernel(const float* __restrict__ W_in,
                            const float* __restrict__ W_ih,
                            const float* __restrict__ W_hh) {
    int i = blockIdx.x * blockDim.x + threadIdx.x;
    if (i < NPOSE * NHID) {
        int k = i / NHID, j = i % NHID;
        float w = W_in[j * NIN + k];
        g_Wptd[i] = make_float2(w, w);
    }
    if (i < NCTX * NHID) {
        int k = i / NHID, j = i % NHID;
        float w = W_in[j * NIN + NPOSE + k];
        g_Wctd[i] = make_float2(w, w);
    }
    if (i < NHID * NHID) {
        int k = i / NHID, j = i % NHID;
        g_W4[i] = make_float4(W_ih[(size_t)(0 * NHID + j) * NHID + k],
                              W_ih[(size_t)(1 * NHID + j) * NHID + k],
                              W_ih[(size_t)(2 * NHID + j) * NHID + k],
                              W_hh[(size_t)(0 * NHID + j) * NHID + k]);
        g_W2[i] = make_float2(W_hh[(size_t)(1 * NHID + j) * NHID + k],
                              W_hh[(size_t)(2 * NHID + j) * NHID + k]);
    }
}

// Load this half's 14 rows of a 28-float smem row as 7 float2 pairs.
// Half 0: rows 0..13  = f4@0, f4@4, f4@8, f2@12
// Half 1: rows 14..27 = f2@14, f4@16, f4@20, f4@24   (all naturally aligned)
template<int HALF>
__device__ __forceinline__ void load7(const float* __restrict__ row, float2* v) {
    if (HALF == 0) {
        float4 a = *reinterpret_cast<const float4*>(row);
        float4 b = *reinterpret_cast<const float4*>(row + 4);
        float4 c = *reinterpret_cast<const float4*>(row + 8);
        float2 d = *reinterpret_cast<const float2*>(row + 12);
        v[0] = make_float2(a.x, a.y); v[1] = make_float2(a.z, a.w);
        v[2] = make_float2(b.x, b.y); v[3] = make_float2(b.z, b.w);
        v[4] = make_float2(c.x, c.y); v[5] = make_float2(c.z, c.w);
        v[6] = d;
    } else {
        float2 d = *reinterpret_cast<const float2*>(row + 14);
        float4 a = *reinterpret_cast<const float4*>(row + 16);
        float4 b = *reinterpret_cast<const float4*>(row + 20);
        float4 c = *reinterpret_cast<const float4*>(row + 24);
        v[0] = d;
        v[1] = make_float2(a.x, a.y); v[2] = make_float2(a.z, a.w);
        v[3] = make_float2(b.x, b.y); v[4] = make_float2(b.z, b.w);
        v[5] = make_float2(c.x, c.y); v[6] = make_float2(c.z, c.w);
    }
}

// Dense input GEMM column for unit j over this half's 14 rows.
template<int HALF>
__device__ __forceinline__ void gemm_in(const float2* __restrict__ Wd, int nk,
                                        const float* __restrict__ src, int j,
                                        float2* ax)
{
    #pragma unroll 4
    for (int k = 0; k < nk; k++) {
        float2 w2 = Wd[k * NHID + j];
        float2 v[7];
        load7<HALF>(src + k * BT, v);
        #pragma unroll
        for (int p = 0; p < 7; p++) ax[p] = ffma2(v[p], w2, ax[p]);
    }
}

// Phase B (six gate GEMM columns) + Phase C (GRU pointwise), unit j, 14 rows.
// Weight stream is software-pipelined TWO k ahead: per-warp latency cover
// ~2 loop bodies (~192 cyc) x 4 warps/SMSP comfortably beats L2 ~234 cyc.
template<int HALF>
__device__ __forceinline__ void gru_step(const float* __restrict__ s_x,
                                         const float* __restrict__ hprev,
                                         float*       __restrict__ hnext,
                                         int j,
                                         float brz0, float brz1,
                                         float bin_, float bhn)
{
    float2 ar[7], az[7], ani[7], anh[7];
    #pragma unroll
    for (int p = 0; p < 7; p++) {
        ar[p] = make_float2(0.f, 0.f);
        az[p] = ar[p]; ani[p] = ar[p]; anh[p] = ar[p];
    }

    const float4* __restrict__ p4 = g_W4 + j;
    const float2* __restrict__ p2 = g_W2 + j;
    float4 wa0 = p4[0],    wa1 = p4[NHID];     // k=0, k=1 in flight
    float2 wb0 = p2[0],    wb1 = p2[NHID];

    #pragma unroll 2
    for (int k = 0; k < NHID; k++) {
        int kp = (k + 2 < NHID) ? (k + 2) : k;  // clamped tail prefetch (L1 hit)
        float4 wa_n = p4[(size_t)kp * NHID];
        float2 wb_n = p2[(size_t)kp * NHID];

        // duplicate to lane pairs on the alu pipe (fma pipe untouched)
        float2 wir = make_float2(wa0.x, wa0.x);
        float2 wiz = make_float2(wa0.y, wa0.y);
        float2 win = make_float2(wa0.z, wa0.z);
        float2 whr = make_float2(wa0.w, wa0.w);
        float2 whz = make_float2(wb0.x, wb0.x);
        float2 whn = make_float2(wb0.y, wb0.y);

        float2 xp[7], hp[7];
        load7<HALF>(s_x   + k * BT, xp);       // LDS broadcast (conflict-free)
        load7<HALF>(hprev + k * BT, hp);

        #pragma unroll
        for (int p = 0; p < 7; p++) {
            ar [p] = ffma2(xp[p], wir, ar [p]);
            ar [p] = ffma2(hp[p], whr, ar [p]);
            az [p] = ffma2(xp[p], wiz, az [p]);
            az [p] = ffma2(hp[p], whz, az [p]);
            ani[p] = ffma2(xp[p], win, ani[p]);
            anh[p] = ffma2(hp[p], whn, anh[p]);
        }
        wa0 = wa1; wb0 = wb1;                   // rotate pipeline
        wa1 = wa_n; wb1 = wb_n;
    }

    // GRU pointwise, registers only
    const float2* hop = reinterpret_cast<const float2*>(hprev + j * BT) + HALF * 7;
    float2*       hnp = reinterpret_cast<float2*>(hnext + j * BT) + HALF * 7;
    #pragma unroll
    for (int p = 0; p < 7; p++) {
        float2 ho = hop[p];
        float rr = sigm(ar[p].x + brz0);
        float zz = sigm(az[p].x + brz1);
        float nn = tanh_acc(ani[p].x + bin_ + rr * (anh[p].x + bhn));
        float hx = (1.0f - zz) * nn + zz * ho.x;
        rr = sigm(ar[p].y + brz0);
        zz = sigm(az[p].y + brz1);
        nn = tanh_acc(ani[p].y + bin_ + rr * (anh[p].y + bhn));
        float hy = (1.0f - zz) * nn + zz * ho.y;
        hnp[p] = make_float2(hx, hy);
    }
}

__global__ __launch_bounds__(NTHR, 1)
void rnn_kernel(const float* __restrict__ last_pose,
                const float* __restrict__ context,
                const int*   __restrict__ d_nf,
                const float* __restrict__ b_in,
                const float* __restrict__ b_ih,
                const float* __restrict__ b_hh,
                const float* __restrict__ W_out,
                const float* __restrict__ b_out,
                float*       __restrict__ out)
{
    extern __shared__ float sm[];
    float* s_cb   = sm;                     // [256][28]  c_base = Wc@ctx + b_in
    float* s_x    = s_cb  + NHID * BT;      // [256][28]  x (temp: raw ctx at init)
    float* s_h0   = s_x   + NHID * BT;      // [256][28]  h ping
    float* s_h1   = s_h0  + NHID * BT;      // [256][28]  h pong
    float* s_pose = s_h1  + NHID * BT;      // [16][28]   pose (13 used)

    const int tid  = threadIdx.x;
    const int j    = tid & (NHID - 1);      // hidden unit owned by this thread
    const int half = tid >> 8;              // 0: rows 0..13, 1: rows 14..27
    const int r0   = half * 14;
    const int row0 = blockIdx.x * BT;
    const int nf   = d_nf[0];

    // --- init: raw ctx -> s_x (transposed), h=0; pose -> s_pose ---
    #pragma unroll
    for (int rr = 0; rr < 14; rr++) {
        int r = r0 + rr;
        int grow = row0 + r; if (grow > NB - 1) grow = NB - 1;   // clamp pad rows
        s_x [j * BT + r] = context[(size_t)grow * NCTX + j];
        s_h0[j * BT + r] = 0.0f;
    }
    if (tid < NPOSE * BT) {
        int p = tid / BT, r = tid - p * BT;
        int grow = row0 + r; if (grow > NB - 1) grow = NB - 1;
        s_pose[p * BT + r] = last_pose[(size_t)grow * NPOSE + p];
    }
    const float binj = b_in[j];
    const float brz0 = b_ih[j]        + b_hh[j];          // fused r bias
    const float brz1 = b_ih[NHID + j] + b_hh[NHID + j];   // fused z bias
    const float bin_ = b_ih[2 * NHID + j];
    const float bhn  = b_hh[2 * NHID + j];
    __syncthreads();

    // --- precompute c_base = Wc @ ctx + b_in (hoisted out of the time loop) ---
    {
        float2 cb[7];
        #pragma unroll
        for (int p = 0; p < 7; p++) cb[p] = make_float2(binj, binj);
        if (half == 0) gemm_in<0>(g_Wctd, NCTX, s_x, j, cb);
        else           gemm_in<1>(g_Wctd, NCTX, s_x, j, cb);
        float2* co = reinterpret_cast<float2*>(s_cb + j * BT) + half * 7;
        #pragma unroll
        for (int p = 0; p < 7; p++) co[p] = cb[p];
    }
    __syncthreads();

    for (int t = 0; t < nf; t++) {
        const float* hprev = (t & 1) ? s_h1 : s_h0;
        float*       hnext = (t & 1) ? s_h0 : s_h1;

        // ---- Phase A: x = relu(c_base + Wp @ pose), 13 k-iterations ----
        {
            float2 ax[7];
            const float2* cb = reinterpret_cast<const float2*>(s_cb + j * BT) + half * 7;
            #pragma unroll
            for (int p = 0; p < 7; p++) ax[p] = cb[p];
            if (half == 0) gemm_in<0>(g_Wptd, NPOSE, s_pose, j, ax);
            else           gemm_in<1>(g_Wptd, NPOSE, s_pose, j, ax);
            float2* xo = reinterpret_cast<float2*>(s_x + j * BT) + half * 7;
            #pragma unroll
            for (int p = 0; p < 7; p++)
                xo[p] = make_float2(fmaxf(ax[p].x, 0.0f), fmaxf(ax[p].y, 0.0f));
        }
        __syncthreads();

        // ---- Phase B + C: gate GEMMs + GRU pointwise (balanced 14/14 rows) ----
        if (half == 0) gru_step<0>(s_x, hprev, hnext, j, brz0, brz1, bin_, bhn);
        else           gru_step<1>(s_x, hprev, hnext, j, brz0, brz1, bin_, bhn);
        __syncthreads();

        // ---- Phase D (fused): pose delta + quaternion normalize via shuffles ----
        // Lane map: r = tid>>4 (0..27), p = tid&15. A row's quaternion components
        // sit in one 16-lane group -> shfl replaces the smem round-trip.
        if (tid < BT * 16) {                  // 448 threads = warps 0..13 (full warps)
            int r = tid >> 4, p = tid & 15;
            int pc = (p < 13) ? p : 12;       // dummy lanes compute harmlessly
            const float4* wo = reinterpret_cast<const float4*>(W_out + pc * NHID);
            float a0 = b_out[pc], a1 = 0.f, a2 = 0.f, a3 = 0.f;
            #pragma unroll 4
            for (int k4 = 0; k4 < NHID / 4; k4++) {
                float4 w4 = wo[k4];
                int kb = k4 * 4;
                a0 = fmaf(hnext[(kb    ) * BT + r], w4.x, a0);
                a1 = fmaf(hnext[(kb + 1) * BT + r], w4.y, a1);
                a2 = fmaf(hnext[(kb + 2) * BT + r], w4.z, a2);
                a3 = fmaf(hnext[(kb + 3) * BT + r], w4.w, a3);
            }
            float raw = s_pose[pc * BT + r] + ((a0 + a1) + (a2 + a3));

            int lane = tid & 31;
            int base = lane & 0x10;           // 16-lane group of this row
            float q3 = __shfl_sync(0xFFFFFFFFu, raw, base + 3);
            float q4 = __shfl_sync(0xFFFFFFFFu, raw, base + 4);
            float q5 = __shfl_sync(0xFFFFFFFFu, raw, base + 5);
            float q6 = __shfl_sync(0xFFFFFFFFu, raw, base + 6);
            float v = raw;
            if (p >= 3 && p <= 6) {
                float nrm = fmaxf(sqrtf(q3*q3 + q4*q4 + q5*q5 + q6*q6), 1e-12f);
                v = raw / nrm;
            }
            if (p < 13) {
                s_pose[p * BT + r] = v;
                int grow = row0 + r;
                if (grow < NB)
                    out[((size_t)grow * nf + t) * NPOSE + p] = v;
            }
        }
        __syncthreads();
    }
}

extern "C" void kernel_launch(void* const* d_in, const int* in_sizes, int n_in,
                              void* d_out, int out_size) {
    const float* last_pose = (const float*)d_in[0];
    const float* context   = (const float*)d_in[1];
    const int*   num_fut   = (const int*)  d_in[2];
    const float* W_in      = (const float*)d_in[3];
    const float* b_in      = (const float*)d_in[4];
    const float* W_ih      = (const float*)d_in[5];
    const float* b_ih      = (const float*)d_in[6];
    const float* W_hh      = (const float*)d_in[7];
    const float* b_hh      = (const float*)d_in[8];
    const float* W_out     = (const float*)d_in[9];
    const float* b_out     = (const float*)d_in[10];
    float* out = (float*)d_out;

    // packed weight transposes (L2-resident, deterministic each call)
    prep_kernel<<<(NHID * NHID + 255) / 256, 256>>>(W_in, W_ih, W_hh);

    const int smem_bytes = (4 * NHID * BT + 16 * BT) * (int)sizeof(float);
    cudaFuncSetAttribute(rnn_kernel,
                         cudaFuncAttributeMaxDynamicSharedMemorySize, smem_bytes);

    const int grid = (NB + BT - 1) / BT;   // 147 CTAs -> one wave
    rnn_kernel<<<grid, NTHR, smem_bytes>>>(last_pose, context, num_fut,
                                           b_in, b_ih, b_hh, W_out, b_out, out);
}

// round 12
// speedup vs baseline: 1.0659x; 1.0659x over previous
#include <cuda_runtime.h>

#define NB    4096
#define NPOSE 13
#define NHID  256
#define NIN   269
#define NCTX  256
#define BT    28      // batch rows per CTA
#define NTHR  512     // two halves: half 0 -> rows 0..13, half 1 -> rows 14..27

// Input-layer weights duplicated (tiny: 13 k-iters + one-time 256 k-iters).
__device__ float2 g_Wptd[NPOSE * NHID];          // W_in pose part: [k][j] -> (w,w)
__device__ float2 g_Wctd[NCTX  * NHID];          // W_in ctx  part: [k][j] -> (w,w)
// Gate weights PACKED, non-duplicated: 2 LDGs per k per thread.
__device__ float4 g_W4[NHID * NHID];             // [k][j] -> (w_ir, w_iz, w_in, w_hr)
__device__ float2 g_W2[NHID * NHID];             // [k][j] -> (w_hz, w_hn)

// Packed dual-fp32 FMA (Blackwell f32x2 pipe; only reachable via PTX).
__device__ __forceinline__ float2 ffma2(float2 a, float2 b, float2 c) {
    float2 d;
    asm("fma.rn.f32x2 %0, %1, %2, %3;"
        : "=l"(*reinterpret_cast<unsigned long long*>(&d))
        : "l"(*reinterpret_cast<unsigned long long*>(&a)),
          "l"(*reinterpret_cast<unsigned long long*>(&b)),
          "l"(*reinterpret_cast<unsigned long long*>(&c)));
    return d;
}

__device__ __forceinline__ float sigm(float a) {
    return 1.0f / (1.0f + __expf(-a));
}
__device__ __forceinline__ float tanh_acc(float a) {
    float e = __expf(-2.0f * fabsf(a));      // e in (0,1], overflow-safe
    float t = (1.0f - e) / (1.0f + e);
    return copysignf(t, a);
}

__global__ void prep_kernel(const float* __restrict__ W_in,
                            const float* __restrict__ W_ih,
                            const float* __restrict__ W_hh) {
    int i = blockIdx.x * blockDim.x + threadIdx.x;
    if (i < NPOSE * NHID) {
        int k = i / NHID, j = i % NHID;
        float w = W_in[j * NIN + k];
        g_Wptd[i] = make_float2(w, w);
    }
    if (i < NCTX * NHID) {
        int k = i / NHID, j = i % NHID;
        float w = W_in[j * NIN + NPOSE + k];
        g_Wctd[i] = make_float2(w, w);
    }
    if (i < NHID * NHID) {
        int k = i / NHID, j = i % NHID;
        g_W4[i] = make_float4(W_ih[(size_t)(0 * NHID + j) * NHID + k],
                              W_ih[(size_t)(1 * NHID + j) * NHID + k],
                              W_ih[(size_t)(2 * NHID + j) * NHID + k],
                              W_hh[(size_t)(0 * NHID + j) * NHID + k]);
        g_W2[i] = make_float2(W_hh[(size_t)(1 * NHID + j) * NHID + k],
                              W_hh[(size_t)(2 * NHID + j) * NHID + k]);
    }
}

// Dense input GEMM column for unit j over this half's 14 rows.
// Half 0: rows 0..13 = f4@0, f4@4, f4@8, f2@12 ; half 1: f2@14, f4@16, f4@20, f4@24.
template<int HALF>
__device__ __forceinline__ void gemm_in(const float2* __restrict__ Wd, int nk,
                                        const float* __restrict__ src, int j,
                                        float2* ax)
{
    #pragma unroll 4
    for (int k = 0; k < nk; k++) {
        float2 w2 = Wd[k * NHID + j];
        const float* row = src + k * BT;
        if (HALF == 0) {
            float4 a = *reinterpret_cast<const float4*>(row);
            float4 b = *reinterpret_cast<const float4*>(row + 4);
            float4 c = *reinterpret_cast<const float4*>(row + 8);
            float2 d = *reinterpret_cast<const float2*>(row + 12);
            ax[0] = ffma2(make_float2(a.x, a.y), w2, ax[0]);
            ax[1] = ffma2(make_float2(a.z, a.w), w2, ax[1]);
            ax[2] = ffma2(make_float2(b.x, b.y), w2, ax[2]);
            ax[3] = ffma2(make_float2(b.z, b.w), w2, ax[3]);
            ax[4] = ffma2(make_float2(c.x, c.y), w2, ax[4]);
            ax[5] = ffma2(make_float2(c.z, c.w), w2, ax[5]);
            ax[6] = ffma2(d, w2, ax[6]);
        } else {
            float2 d = *reinterpret_cast<const float2*>(row + 14);
            float4 a = *reinterpret_cast<const float4*>(row + 16);
            float4 b = *reinterpret_cast<const float4*>(row + 20);
            float4 c = *reinterpret_cast<const float4*>(row + 24);
            ax[0] = ffma2(d, w2, ax[0]);
            ax[1] = ffma2(make_float2(a.x, a.y), w2, ax[1]);
            ax[2] = ffma2(make_float2(a.z, a.w), w2, ax[2]);
            ax[3] = ffma2(make_float2(b.x, b.y), w2, ax[3]);
            ax[4] = ffma2(make_float2(b.z, b.w), w2, ax[4]);
            ax[5] = ffma2(make_float2(c.x, c.y), w2, ax[5]);
            ax[6] = ffma2(make_float2(c.z, c.w), w2, ax[6]);
        }
    }
}

// Phase B (six gate GEMM columns) + Phase C (GRU pointwise), unit j, 14 rows.
// Weight stream software-pipelined ONE k ahead (R7-proven); balanced halves.
template<int HALF>
__device__ __forceinline__ void gru_step(const float* __restrict__ s_x,
                                         const float* __restrict__ hprev,
                                         float*       __restrict__ hnext,
                                         int j,
                                         float brz0, float brz1,
                                         float bin_, float bhn)
{
    float2 ar[7], az[7], ani[7], anh[7];
    #pragma unroll
    for (int p = 0; p < 7; p++) {
        ar[p] = make_float2(0.f, 0.f);
        az[p] = ar[p]; ani[p] = ar[p]; anh[p] = ar[p];
    }

    const float4* __restrict__ p4 = g_W4 + j;
    const float2* __restrict__ p2 = g_W2 + j;
    float4 wa = p4[0];                     // k = 0 preload
    float2 wb = p2[0];

    #pragma unroll 2
    for (int k = 0; k < NHID; k++) {
        int kn = (k < NHID - 1) ? (k + 1) : k;   // clamped tail (L1 hit)
        float4 wa_n = p4[(size_t)kn * NHID];
        float2 wb_n = p2[(size_t)kn * NHID];

        // duplicate to lane pairs on the alu pipe (fma pipe untouched)
        float2 wir = make_float2(wa.x, wa.x);
        float2 wiz = make_float2(wa.y, wa.y);
        float2 win = make_float2(wa.z, wa.z);
        float2 whr = make_float2(wa.w, wa.w);
        float2 whz = make_float2(wb.x, wb.x);
        float2 whn = make_float2(wb.y, wb.y);

        const float* xrow = s_x   + k * BT;
        const float* hrow = hprev + k * BT;
        #pragma unroll
        for (int blk = 0; blk < 4; blk++) {
            // block layout per half: half0 {f4,f4,f4,f2}, half1 {f2,f4,f4,f4}
            if (HALF == 0 ? (blk < 3) : (blk > 0)) {
                int off = (HALF == 0) ? blk * 4 : (12 + blk * 4);
                float4 xv = *reinterpret_cast<const float4*>(xrow + off);
                float4 hv = *reinterpret_cast<const float4*>(hrow + off);
                int p0 = (HALF == 0) ? blk * 2 : blk * 2 - 1;
                float2 x0 = make_float2(xv.x, xv.y), x1 = make_float2(xv.z, xv.w);
                float2 h0 = make_float2(hv.x, hv.y), h1 = make_float2(hv.z, hv.w);
                ar [p0]   = ffma2(x0, wir, ar [p0]);
                ar [p0]   = ffma2(h0, whr, ar [p0]);
                ar [p0+1] = ffma2(x1, wir, ar [p0+1]);
                ar [p0+1] = ffma2(h1, whr, ar [p0+1]);
                az [p0]   = ffma2(x0, wiz, az [p0]);
                az [p0]   = ffma2(h0, whz, az [p0]);
                az [p0+1] = ffma2(x1, wiz, az [p0+1]);
                az [p0+1] = ffma2(h1, whz, az [p0+1]);
                ani[p0]   = ffma2(x0, win, ani[p0]);
                ani[p0+1] = ffma2(x1, win, ani[p0+1]);
                anh[p0]   = ffma2(h0, whn, anh[p0]);
                anh[p0+1] = ffma2(h1, whn, anh[p0+1]);
            } else {
                int off = (HALF == 0) ? 12 : 14;
                int p0  = (HALF == 0) ? 6 : 0;
                float2 xv = *reinterpret_cast<const float2*>(xrow + off);
                float2 hv = *reinterpret_cast<const float2*>(hrow + off);
                ar [p0] = ffma2(xv, wir, ar [p0]);
                ar [p0] = ffma2(hv, whr, ar [p0]);
                az [p0] = ffma2(xv, wiz, az [p0]);
                az [p0] = ffma2(hv, whz, az [p0]);
                ani[p0] = ffma2(xv, win, ani[p0]);
                anh[p0] = ffma2(hv, whn, anh[p0]);
            }
        }
        wa = wa_n;
        wb = wb_n;
    }

    // GRU pointwise, registers only
    const float2* hop = reinterpret_cast<const float2*>(hprev + j * BT) + HALF * 7;
    float2*       hnp = reinterpret_cast<float2*>(hnext + j * BT) + HALF * 7;
    #pragma unroll
    for (int p = 0; p < 7; p++) {
        float2 ho = hop[p];
        float rr = sigm(ar[p].x + brz0);
        float zz = sigm(az[p].x + brz1);
        float nn = tanh_acc(ani[p].x + bin_ + rr * (anh[p].x + bhn));
        float hx = (1.0f - zz) * nn + zz * ho.x;
        rr = sigm(ar[p].y + brz0);
        zz = sigm(az[p].y + brz1);
        nn = tanh_acc(ani[p].y + bin_ + rr * (anh[p].y + bhn));
        float hy = (1.0f - zz) * nn + zz * ho.y;
        hnp[p] = make_float2(hx, hy);
    }
}

__global__ __launch_bounds__(NTHR, 1)
void rnn_kernel(const float* __restrict__ last_pose,
                const float* __restrict__ context,
                const int*   __restrict__ d_nf,
                const float* __restrict__ b_in,
                const float* __restrict__ b_ih,
                const float* __restrict__ b_hh,
                const float* __restrict__ W_out,
                const float* __restrict__ b_out,
                float*       __restrict__ out)
{
    extern __shared__ float sm[];
    float* s_cb   = sm;                     // [256][28]  c_base = Wc@ctx + b_in
    float* s_x    = s_cb  + NHID * BT;      // [256][28]  x (temp: raw ctx at init)
    float* s_h0   = s_x   + NHID * BT;      // [256][28]  h ping
    float* s_h1   = s_h0  + NHID * BT;      // [256][28]  h pong
    float* s_pose = s_h1  + NHID * BT;      // [16][28]   pose (13 used)

    const int tid  = threadIdx.x;
    const int j    = tid & (NHID - 1);      // hidden unit owned by this thread
    const int half = tid >> 8;              // 0: rows 0..13, 1: rows 14..27
    const int r0   = half * 14;
    const int row0 = blockIdx.x * BT;
    const int nf   = d_nf[0];

    // --- init: raw ctx -> s_x (transposed), h=0; pose -> s_pose ---
    #pragma unroll
    for (int rr = 0; rr < 14; rr++) {
        int r = r0 + rr;
        int grow = row0 + r; if (grow > NB - 1) grow = NB - 1;   // clamp pad rows
        s_x [j * BT + r] = context[(size_t)grow * NCTX + j];
        s_h0[j * BT + r] = 0.0f;
    }
    if (tid < NPOSE * BT) {
        int p = tid / BT, r = tid - p * BT;
        int grow = row0 + r; if (grow > NB - 1) grow = NB - 1;
        s_pose[p * BT + r] = last_pose[(size_t)grow * NPOSE + p];
    }
    const float binj = b_in[j];
    const float brz0 = b_ih[j]        + b_hh[j];          // fused r bias
    const float brz1 = b_ih[NHID + j] + b_hh[NHID + j];   // fused z bias
    const float bin_ = b_ih[2 * NHID + j];
    const float bhn  = b_hh[2 * NHID + j];
    __syncthreads();

    // --- precompute c_base = Wc @ ctx + b_in (hoisted out of the time loop) ---
    {
        float2 cb[7];
        #pragma unroll
        for (int p = 0; p < 7; p++) cb[p] = make_float2(binj, binj);
        if (half == 0) gemm_in<0>(g_Wctd, NCTX, s_x, j, cb);
        else           gemm_in<1>(g_Wctd, NCTX, s_x, j, cb);
        float2* co = reinterpret_cast<float2*>(s_cb + j * BT) + half * 7;
        #pragma unroll
        for (int p = 0; p < 7; p++) co[p] = cb[p];
    }
    __syncthreads();

    for (int t = 0; t < nf; t++) {
        const float* hprev = (t & 1) ? s_h1 : s_h0;
        float*       hnext = (t & 1) ? s_h0 : s_h1;

        // ---- Phase A: x = relu(c_base + Wp @ pose), 13 k-iterations ----
        {
            float2 ax[7];
            const float2* cb = reinterpret_cast<const float2*>(s_cb + j * BT) + half * 7;
            #pragma unroll
            for (int p = 0; p < 7; p++) ax[p] = cb[p];
            if (half == 0) gemm_in<0>(g_Wptd, NPOSE, s_pose, j, ax);
            else           gemm_in<1>(g_Wptd, NPOSE, s_pose, j, ax);
            float2* xo = reinterpret_cast<float2*>(s_x + j * BT) + half * 7;
            #pragma unroll
            for (int p = 0; p < 7; p++)
                xo[p] = make_float2(fmaxf(ax[p].x, 0.0f), fmaxf(ax[p].y, 0.0f));
        }
        __syncthreads();

        // ---- Phase B + C: gate GEMMs + GRU pointwise (balanced 14/14 rows) ----
        if (half == 0) gru_step<0>(s_x, hprev, hnext, j, brz0, brz1, bin_, bhn);
        else           gru_step<1>(s_x, hprev, hnext, j, brz0, brz1, bin_, bhn);
        __syncthreads();

        // ---- Phase D (fused): pose delta + quaternion normalize via shuffles ----
        // Lane map: r = tid>>4 (0..27), p = tid&15. A row's quaternion components
        // sit in one 16-lane group -> shfl replaces the smem round-trip.
        if (tid < BT * 16) {                  // 448 threads = warps 0..13 (full warps)
            int r = tid >> 4, p = tid & 15;
            int pc = (p < 13) ? p : 12;       // dummy lanes compute harmlessly
            const float4* wo = reinterpret_cast<const float4*>(W_out + pc * NHID);
            float a0 = b_out[pc], a1 = 0.f, a2 = 0.f, a3 = 0.f;
            #pragma unroll 4
            for (int k4 = 0; k4 < NHID / 4; k4++) {
                float4 w4 = wo[k4];
                int kb = k4 * 4;
                a0 = fmaf(hnext[(kb    ) * BT + r], w4.x, a0);
                a1 = fmaf(hnext[(kb + 1) * BT + r], w4.y, a1);
                a2 = fmaf(hnext[(kb + 2) * BT + r], w4.z, a2);
                a3 = fmaf(hnext[(kb + 3) * BT + r], w4.w, a3);
            }
            float raw = s_pose[pc * BT + r] + ((a0 + a1) + (a2 + a3));

            int lane = tid & 31;
            int base = lane & 0x10;           // 16-lane group of this row
            float q3 = __shfl_sync(0xFFFFFFFFu, raw, base + 3);
            float q4 = __shfl_sync(0xFFFFFFFFu, raw, base + 4);
            float q5 = __shfl_sync(0xFFFFFFFFu, raw, base + 5);
            float q6 = __shfl_sync(0xFFFFFFFFu, raw, base + 6);
            float v = raw;
            if (p >= 3 && p <= 6) {
                float nrm = fmaxf(sqrtf(q3*q3 + q4*q4 + q5*q5 + q6*q6), 1e-12f);
                v = raw / nrm;
            }
            if (p < 13) {
                s_pose[p * BT + r] = v;
                int grow = row0 + r;
                if (grow < NB)
                    out[((size_t)grow * nf + t) * NPOSE + p] = v;
            }
        }
        __syncthreads();
    }
}

extern "C" void kernel_launch(void* const* d_in, const int* in_sizes, int n_in,
                              void* d_out, int out_size) {
    const float* last_pose = (const float*)d_in[0];
    const float* context   = (const float*)d_in[1];
    const int*   num_fut   = (const int*)  d_in[2];
    const float* W_in      = (const float*)d_in[3];
    const float* b_in      = (const float*)d_in[4];
    const float* W_ih      = (const float*)d_in[5];
    const float* b_ih      = (const float*)d_in[6];
    const float* W_hh      = (const float*)d_in[7];
    const float* b_hh      = (const float*)d_in[8];
    const float* W_out     = (const float*)d_in[9];
    const float* b_out     = (const float*)d_in[10];
    float* out = (float*)d_out;

    // packed weight transposes (L2-resident, deterministic each call)
    prep_kernel<<<(NHID * NHID + 255) / 256, 256>>>(W_in, W_ih, W_hh);

    const int smem_bytes = (4 * NHID * BT + 16 * BT) * (int)sizeof(float);
    cudaFuncSetAttribute(rnn_kernel,
                         cudaFuncAttributeMaxDynamicSharedMemorySize, smem_bytes);

    const int grid = (NB + BT - 1) / BT;   // 147 CTAs -> one wave
    rnn_kernel<<<grid, NTHR, smem_bytes>>>(last_pose, context, num_fut,
                                           b_in, b_ih, b_hh, W_out, b_out, out);
}